// round 12
// baseline (speedup 1.0000x reference)
#include <cuda_runtime.h>
#include <cuda_bf16.h>
#include <cuda_fp16.h>
#include <math.h>
#include <stdint.h>

#define MAX_N  50048
#define MAX_E  800000
#define MAX_NI 2048

__device__ float g_xa  [MAX_N * 256];
__device__ float g_qa  [MAX_N * 256];
__device__ __half g_kvh[MAX_N * 512];
__device__ float g_za  [MAX_N * 256];
__device__ float g_bf  [512];
__device__ __nv_bfloat16 g_xp_hl [MAX_N * 512];
__device__ __nv_bfloat16 g_xa_hl [MAX_N * 512];
__device__ __nv_bfloat16 g_agg_hl[MAX_N * 512];
__device__ __nv_bfloat16 g_za_hl [MAX_N * 512];
__device__ __nv_bfloat16 g_zin_hl[MAX_NI * 512];
__device__ __nv_bfloat16 g_wft_hl [512 * 512];
__device__ __nv_bfloat16 g_winp_hl[256 * 256];
__device__ __nv_bfloat16 g_wina_hl[256 * 256];
__device__ __nv_bfloat16 g_wq_hl  [256 * 512];
__device__ __nv_bfloat16 g_wout_hl[256 * 512];
__device__ int   g_deg [MAX_N + 1];
__device__ int   g_off [MAX_N + 1];
__device__ int   g_cur [MAX_N];
__device__ int   g_csr [MAX_E];

__device__ __forceinline__ void split2(float f0, float f1,
                                       uint32_t& hi, uint32_t& lo)
{
    uint32_t b0 = __float_as_uint(f0), b1 = __float_as_uint(f1);
    hi = __byte_perm(b0, b1, 0x7632);
    float r0 = f0 - __uint_as_float(b0 & 0xFFFF0000u);
    float r1 = f1 - __uint_as_float(b1 & 0xFFFF0000u);
    __nv_bfloat162 t = __floats2bfloat162_rn(r0, r1);
    lo = *(uint32_t*)&t;
}

__device__ __forceinline__ uint32_t smem_u32(const void* p) {
    uint32_t a;
    asm("{ .reg .u64 t; cvta.to.shared.u64 t, %1; cvt.u32.u64 %0, t; }"
        : "=r"(a) : "l"(p));
    return a;
}

#define LDSM4(r0, r1, r2, r3, addr) \
    asm volatile("ldmatrix.sync.aligned.m8n8.x4.shared.b16 {%0,%1,%2,%3}, [%4];" \
                 : "=r"(r0), "=r"(r1), "=r"(r2), "=r"(r3) : "r"(addr))

#define MMA16816(acc, a0, a1, a2, a3, b0, b1) \
    asm volatile("mma.sync.aligned.m16n8k16.row.col.f32.bf16.bf16.f32 " \
                 "{%0,%1,%2,%3}, {%4,%5,%6,%7}, {%8,%9}, {%0,%1,%2,%3};\n" \
                 : "+f"((acc)[0]), "+f"((acc)[1]), "+f"((acc)[2]), "+f"((acc)[3]) \
                 : "r"(a0), "r"(a1), "r"(a2), "r"(a3), "r"(b0), "r"(b1))

#define CPASYNC16(smem, gptr) \
    asm volatile("cp.async.cg.shared.global [%0], [%1], 16;" \
                 :: "r"(smem), "l"(gptr) : "memory")
#define CPASYNC_COMMIT() asm volatile("cp.async.commit_group;" ::: "memory")
#define CPASYNC_WAIT0()  asm volatile("cp.async.wait_group 0;" ::: "memory")

#define SMSTR 40

struct GP {
    const float* A; int lda;
    const __nv_bfloat16* Ahl;
    const __nv_bfloat16* B;
    float* C; __half* Ch; __nv_bfloat16* Chl;
    int ldc;
    const float* bias; int act;
    int M, N, K;
    const float* aux; const float* skipp;
};

template <bool AHL>
__global__ void __launch_bounds__(256, 2)
mm_nt(GP p0, GP p1)
{
    __shared__ __align__(16) __nv_bfloat16 As[2][128 * SMSTR];
    __shared__ __align__(16) __nv_bfloat16 Bs[2][128 * SMSTR];

    const GP p = (blockIdx.z == 0) ? p0 : p1;
    const int n0 = blockIdx.x * 128;
    const int m0 = blockIdx.y * 128;
    if (n0 >= p.N || m0 >= p.M) return;

    const int tid  = threadIdx.x;
    const int warp = tid >> 5, lane = tid & 31;
    const int gq = lane >> 2, tg = lane & 3;
    const int wm = warp >> 1, wn = warp & 1;
    const int l15 = lane & 15, l16 = lane >> 4;

    float acc[2][8][4];
#pragma unroll
    for (int i = 0; i < 2; i++)
#pragma unroll
        for (int j = 0; j < 8; j++)
#pragma unroll
            for (int e = 0; e < 4; e++) acc[i][j][e] = 0.f;

    const int srow = tid >> 1, shalf = tid & 1;
    const float4 z4 = make_float4(0.f, 0.f, 0.f, 0.f);
    const int KT = p.K >> 4;
    const int twoK = 2 * p.K;

    const uint4* bp = (const uint4*)(p.B + (size_t)(n0 + srow) * twoK + shalf * 16);
    const uint32_t bdst0 = smem_u32(&Bs[0][srow * SMSTR + shalf * 16]);
    const uint32_t bdst1 = smem_u32(&Bs[1][srow * SMSTR + shalf * 16]);
    const uint32_t adst0 = smem_u32(&As[0][srow * SMSTR + shalf * 16]);
    const uint32_t adst1 = smem_u32(&As[1][srow * SMSTR + shalf * 16]);

    const bool aok = srow < ((p.M - m0 > 128) ? 128 : (p.M - m0));
    const float* ap = AHL ? nullptr
                          : p.A + (size_t)(m0 + srow) * p.lda + shalf * 8;
    const uint4* aphl = AHL
        ? (const uint4*)(p.Ahl + (size_t)(m0 + srow) * twoK + shalf * 16)
        : nullptr;

    float4 ra0, ra1;

    if (AHL) {
        CPASYNC16(adst0,      aphl);
        CPASYNC16(adst0 + 16, aphl + 1);
        CPASYNC16(bdst0,      bp);
        CPASYNC16(bdst0 + 16, bp + 1);
        CPASYNC_COMMIT();
    } else {
        CPASYNC16(bdst0,      bp);
        CPASYNC16(bdst0 + 16, bp + 1);
        CPASYNC_COMMIT();
        ra0 = aok ? *(const float4*)(ap + 0) : z4;
        ra1 = aok ? *(const float4*)(ap + 4) : z4;
        uint32_t h[4], l[4];
        split2(ra0.x, ra0.y, h[0], l[0]); split2(ra0.z, ra0.w, h[1], l[1]);
        split2(ra1.x, ra1.y, h[2], l[2]); split2(ra1.z, ra1.w, h[3], l[3]);
        uint4* ah = (uint4*)&As[0][srow * SMSTR + shalf * 8];
        ah[0] = make_uint4(h[0], h[1], h[2], h[3]);
        ah[2] = make_uint4(l[0], l[1], l[2], l[3]);
    }
    CPASYNC_WAIT0();
    __syncthreads();

    for (int kt = 0; kt < KT; kt++) {
        const int cur = kt & 1;
        const bool more = (kt + 1 < KT);
        if (more) {
            uint32_t bd = (cur ? bdst0 : bdst1);
            const uint4* b2 = bp + (kt + 1) * 4;
            CPASYNC16(bd,      b2);
            CPASYNC16(bd + 16, b2 + 1);
            if (AHL) {
                uint32_t ad = (cur ? adst0 : adst1);
                const uint4* a2 = aphl + (kt + 1) * 4;
                CPASYNC16(ad,      a2);
                CPASYNC16(ad + 16, a2 + 1);
            } else {
                const float* a2 = ap + (kt + 1) * 16;
                ra0 = aok ? *(const float4*)(a2 + 0) : z4;
                ra1 = aok ? *(const float4*)(a2 + 4) : z4;
            }
            CPASYNC_COMMIT();
        }

        const uint32_t asb = smem_u32(&As[cur][0]);
        const uint32_t bsb = smem_u32(&Bs[cur][0]);

        uint32_t ahf[2][4], alf[2][4];
#pragma unroll
        for (int mt = 0; mt < 2; mt++) {
            int row = wm * 32 + mt * 16 + l15;
            uint32_t a_ad = asb + row * (SMSTR * 2) + l16 * 16;
            LDSM4(ahf[mt][0], ahf[mt][1], ahf[mt][2], ahf[mt][3], a_ad);
            LDSM4(alf[mt][0], alf[mt][1], alf[mt][2], alf[mt][3], a_ad + 32);
        }
#pragma unroll
        for (int npp = 0; npp < 2; npp++) {
            uint32_t bhf[2][4], blf[2][4];
#pragma unroll
            for (int q = 0; q < 2; q++) {
                int row = wn * 64 + (npp * 2 + q) * 16 + l15;
                uint32_t b_ad = bsb + row * (SMSTR * 2) + l16 * 16;
                LDSM4(bhf[q][0], bhf[q][1], bhf[q][2], bhf[q][3], b_ad);
                LDSM4(blf[q][0], blf[q][1], blf[q][2], blf[q][3], b_ad + 32);
            }
#pragma unroll
            for (int q = 0; q < 2; q++)
#pragma unroll
                for (int mt = 0; mt < 2; mt++)
#pragma unroll
                    for (int j = 0; j < 2; j++)
                        MMA16816(acc[mt][(npp * 2 + q) * 2 + j],
                                 ahf[mt][0], ahf[mt][1], ahf[mt][2], ahf[mt][3],
                                 bhf[q][j], bhf[q][2 + j]);
#pragma unroll
            for (int q = 0; q < 2; q++)
#pragma unroll
                for (int mt = 0; mt < 2; mt++)
#pragma unroll
                    for (int j = 0; j < 2; j++)
                        MMA16816(acc[mt][(npp * 2 + q) * 2 + j],
                                 ahf[mt][0], ahf[mt][1], ahf[mt][2], ahf[mt][3],
                                 blf[q][j], blf[q][2 + j]);
#pragma unroll
            for (int q = 0; q < 2; q++)
#pragma unroll
                for (int mt = 0; mt < 2; mt++)
#pragma unroll
                    for (int j = 0; j < 2; j++)
                        MMA16816(acc[mt][(npp * 2 + q) * 2 + j],
                                 alf[mt][0], alf[mt][1], alf[mt][2], alf[mt][3],
                                 bhf[q][j], bhf[q][2 + j]);
        }

        if (more) {
            if (!AHL) {
                const int nxt = 1 - cur;
                uint32_t h[4], l[4];
                split2(ra0.x, ra0.y, h[0], l[0]); split2(ra0.z, ra0.w, h[1], l[1]);
                split2(ra1.x, ra1.y, h[2], l[2]); split2(ra1.z, ra1.w, h[3], l[3]);
                uint4* ah = (uint4*)&As[nxt][srow * SMSTR + shalf * 8];
                ah[0] = make_uint4(h[0], h[1], h[2], h[3]);
                ah[2] = make_uint4(l[0], l[1], l[2], l[3]);
            }
            CPASYNC_WAIT0();
            __syncthreads();
        }
    }

    float ga = 0.f;
    if (p.act == 3) ga = 1.f / (1.f + __expf(-p.skipp[0]));
    // hl output rows are 2*K bf16 = K u32 wide (output feeds K=256 GEMMs)
    const int hlstride = 256;

#pragma unroll
    for (int mt = 0; mt < 2; mt++) {
#pragma unroll
        for (int nt = 0; nt < 8; nt++) {
            int r0 = m0 + wm * 32 + mt * 16 + gq;
            int cc = n0 + wn * 64 + nt * 8 + 2 * tg;
            if (cc < p.N) {
                float b0 = p.bias ? p.bias[cc] : 0.f;
                float b1 = p.bias ? p.bias[cc + 1] : 0.f;
                float v0 = acc[mt][nt][0] + b0, v1 = acc[mt][nt][1] + b1;
                float v2 = acc[mt][nt][2] + b0, v3 = acc[mt][nt][3] + b1;
                if (p.act == 1) {
                    v0 = fmaxf(v0, 0.f); v1 = fmaxf(v1, 0.f);
                    v2 = fmaxf(v2, 0.f); v3 = fmaxf(v3, 0.f);
                } else if (p.act == 2) {
                    v0 = 1.f / (1.f + __expf(-v0)); v1 = 1.f / (1.f + __expf(-v1));
                    v2 = 1.f / (1.f + __expf(-v2)); v3 = 1.f / (1.f + __expf(-v3));
                } else if (p.act == 3) {
                    if (r0 < p.M) {
                        v0 = ga * v0 + (1.f - ga) * p.aux[(size_t)r0 * 256 + cc];
                        v1 = ga * v1 + (1.f - ga) * p.aux[(size_t)r0 * 256 + cc + 1];
                    }
                    if (r0 + 8 < p.M) {
                        v2 = ga * v2 + (1.f - ga) * p.aux[(size_t)(r0 + 8) * 256 + cc];
                        v3 = ga * v3 + (1.f - ga) * p.aux[(size_t)(r0 + 8) * 256 + cc + 1];
                    }
                }
                if (p.Ch) {
                    __half2* Ch = (__half2*)p.Ch;
                    if (r0 < p.M)
                        Ch[((size_t)r0 * p.ldc + cc) >> 1] = __floats2half2_rn(v0, v1);
                    if (r0 + 8 < p.M)
                        Ch[((size_t)(r0 + 8) * p.ldc + cc) >> 1] = __floats2half2_rn(v2, v3);
                }
                if (p.C) {
                    if (r0 < p.M) {
                        float2 q = {v0, v1};
                        *(float2*)&p.C[(size_t)r0 * p.ldc + cc] = q;
                    }
                    if (r0 + 8 < p.M) {
                        float2 q = {v2, v3};
                        *(float2*)&p.C[(size_t)(r0 + 8) * p.ldc + cc] = q;
                    }
                }
                if (p.Chl) {
                    int coff = (cc >> 4) * 16 + ((cc & 15) >> 1);
                    if (r0 < p.M) {
                        uint32_t hi, lo;
                        split2(v0, v1, hi, lo);
                        uint32_t* d = (uint32_t*)p.Chl + (size_t)r0 * hlstride + coff;
                        d[0] = hi; d[8] = lo;
                    }
                    if (r0 + 8 < p.M) {
                        uint32_t hi, lo;
                        split2(v2, v3, hi, lo);
                        uint32_t* d = (uint32_t*)p.Chl + (size_t)(r0 + 8) * hlstride + coff;
                        d[0] = hi; d[8] = lo;
                    }
                }
            }
        }
    }
}

__global__ void tr_all(const float* __restrict__ Wp, const float* __restrict__ Wa,
                       const float* __restrict__ Wq, const float* __restrict__ Wo)
{
    __shared__ float t[32][33];
    const float* in; __nv_bfloat16* out; int ldin, K, N;
    switch (blockIdx.z) {
        case 0: in = Wp; out = g_winp_hl; ldin = 256; K = 128; N = 256; break;
        case 1: in = Wa; out = g_wina_hl; ldin = 256; K = 128; N = 256; break;
        case 2: in = Wq; out = g_wq_hl;   ldin = 768; K = 256; N = 256; break;
        default: in = Wo; out = g_wout_hl; ldin = 256; K = 256; N = 256; break;
    }
    int bx = blockIdx.x * 32, by = blockIdx.y * 32;
    if (bx >= N || by >= K) return;
    int x = bx + threadIdx.x;
    for (int dy = 0; dy < 32; dy += 8) {
        int y = by + threadIdx.y + dy;
        if (x < N && y < K) t[threadIdx.y + dy][threadIdx.x] = in[(size_t)y * ldin + x];
    }
    __syncthreads();
    if (threadIdx.x < 16) {
        for (int dy = 0; dy < 32; dy += 8) {
            int n_ = bx + threadIdx.y + dy;
            int k0 = by + 2 * threadIdx.x;
            if (n_ < N && k0 < K) {
                float f0 = t[2 * threadIdx.x][threadIdx.y + dy];
                float f1 = t[2 * threadIdx.x + 1][threadIdx.y + dy];
                uint32_t hi, lo;
                split2(f0, f1, hi, lo);
                uint32_t* d = (uint32_t*)(out + (size_t)n_ * 2 * K
                                          + (k0 >> 4) * 32 + (k0 & 15));
                d[0] = hi; d[8] = lo;
            }
        }
    }
}

__global__ void fuse_kernel(const float* __restrict__ Wkqv_p,
                            const float* __restrict__ Rk,
                            const float* __restrict__ Rv)
{
    int idx = blockIdx.x * 256 + threadIdx.x;
    int c = idx >> 7;
    int j = idx & 127;
    int isv = c >> 8, h = (c >> 7) & 1, e = c & 127;
    const float* R = (isv ? Rv : Rk) + h * 16384;
    const float* w0 = Wkqv_p + (size_t)(2 * j) * 768 + (isv ? 512 : 0) + h * 128;
    const float* w1 = w0 + 768;
    float s0 = 0.f, s1 = 0.f;
#pragma unroll 8
    for (int d = 0; d < 128; d++) {
        float rv = R[d * 128 + e];
        s0 += w0[d] * rv;
        s1 += w1[d] * rv;
    }
    uint32_t hi, lo;
    split2(s0, s1, hi, lo);
    int k = 2 * j;
    uint32_t* dst = (uint32_t*)(g_wft_hl + (size_t)c * 512 + (k >> 4) * 32 + (k & 15));
    dst[0] = hi; dst[8] = lo;
}

__global__ void bias_fuse_kernel(const float* __restrict__ bkqv,
                                 const float* __restrict__ Rk,
                                 const float* __restrict__ Rv)
{
    int gw = (blockIdx.x * 256 + threadIdx.x) >> 5;
    int lane = threadIdx.x & 31;
    if (gw >= 512) return;
    int isv = gw >> 8, h = (gw >> 7) & 1, e = gw & 127;
    const float* R = (isv ? Rv : Rk) + h * 16384;
    const float* b = bkqv + (isv ? 512 : 0) + h * 128;
    float s = 0.f;
#pragma unroll
    for (int i = 0; i < 4; i++) {
        int d = lane + 32 * i;
        s += b[d] * R[d * 128 + e];
    }
#pragma unroll
    for (int o = 16; o > 0; o >>= 1) s += __shfl_xor_sync(0xffffffffu, s, o);
    if (lane == 0) g_bf[gw] = s;
}

__global__ void zero_deg_kernel(int n)
{
    int i = blockIdx.x * blockDim.x + threadIdx.x;
    if (i <= n) g_deg[i] = 0;
}
__global__ void hist_kernel(const int* __restrict__ dst, int E)
{
    int e = blockIdx.x * blockDim.x + threadIdx.x;
    if (e < E) atomicAdd(&g_deg[dst[e]], 1);
}
__global__ void __launch_bounds__(1024) scan_kernel(int n)
{
    __shared__ int part[1024];
    int t = threadIdx.x;
    int chunk = (n + 1023) >> 10;
    int b = t * chunk, e = min(b + chunk, n);
    int s = 0;
    for (int i = b; i < e; i++) s += g_deg[i];
    part[t] = s;
    __syncthreads();
    for (int o = 1; o < 1024; o <<= 1) {
        int v = (t >= o) ? part[t - o] : 0;
        __syncthreads();
        part[t] += v;
        __syncthreads();
    }
    int run = (t == 0) ? 0 : part[t - 1];
    for (int i = b; i < e; i++) {
        g_off[i] = run; g_cur[i] = run; run += g_deg[i];
    }
    if (t == 0) g_off[n] = part[1023];
}
__global__ void scatter_kernel(const int* __restrict__ src,
                               const int* __restrict__ dst, int E)
{
    int e = blockIdx.x * blockDim.x + threadIdx.x;
    if (e < E) {
        int p = atomicAdd(&g_cur[dst[e]], 1);
        g_csr[p] = src[e];
    }
}

__device__ __forceinline__ float dot8h(const float4& q0, const float4& q1,
                                       const uint4& ck)
{
    float2 k0 = __half22float2(*(const __half2*)&ck.x);
    float2 k1 = __half22float2(*(const __half2*)&ck.y);
    float2 k2 = __half22float2(*(const __half2*)&ck.z);
    float2 k3 = __half22float2(*(const __half2*)&ck.w);
    return q0.x * k0.x + q0.y * k0.y + q0.z * k1.x + q0.w * k1.y
         + q1.x * k2.x + q1.y * k2.y + q1.z * k3.x + q1.w * k3.y;
}

__device__ __forceinline__ void acc8h(float (&a)[8], float w, const uint4& cv)
{
    float2 v0 = __half22float2(*(const __half2*)&cv.x);
    float2 v1 = __half22float2(*(const __half2*)&cv.y);
    float2 v2 = __half22float2(*(const __half2*)&cv.z);
    float2 v3 = __half22float2(*(const __half2*)&cv.w);
    a[0] += w * v0.x; a[1] += w * v0.y;
    a[2] += w * v1.x; a[3] += w * v1.y;
    a[4] += w * v2.x; a[5] += w * v2.y;
    a[6] += w * v3.x; a[7] += w * v3.y;
}

__global__ void attn_kernel(int Na, const float* __restrict__ p_rel)
{
    int gw = (blockIdx.x * 256 + threadIdx.x) >> 5;
    int lane = threadIdx.x & 31;
    if (gw >= Na) return;
    const int dst = gw;
    const int hl = lane >> 4;
    const int l  = lane & 15;

    const int beg = g_off[dst], end = g_off[dst + 1];
    const float scale = p_rel[hl] * 0.08838834764831845f;

    const float* qb = &g_qa[(size_t)dst * 256 + hl * 128 + l * 8];
    const float4 q0 = *(const float4*)qb;
    const float4 q1 = *(const float4*)(qb + 4);

    float m = -INFINITY, ssum = 0.f;
    float a[8] = {0.f, 0.f, 0.f, 0.f, 0.f, 0.f, 0.f, 0.f};

    const size_t base_off = (size_t)hl * 128 + l * 8;

    int p = beg;
    for (; p + 4 <= end; p += 4) {
        const __half* kb0 = &g_kvh[(size_t)g_csr[p]     * 512 + base_off];
        const __half* kb1 = &g_kvh[(size_t)g_csr[p + 1] * 512 + base_off];
        const __half* kb2 = &g_kvh[(size_t)g_csr[p + 2] * 512 + base_off];
        const __half* kb3 = &g_kvh[(size_t)g_csr[p + 3] * 512 + base_off];
        uint4 ck0 = *(const uint4*)kb0, cv0 = *(const uint4*)(kb0 + 256);
        uint4 ck1 = *(const uint4*)kb1, cv1 = *(const uint4*)(kb1 + 256);
        uint4 ck2 = *(const uint4*)kb2, cv2 = *(const uint4*)(kb2 + 256);
        uint4 ck3 = *(const uint4*)kb3, cv3 = *(const uint4*)(kb3 + 256);

        float d0 = dot8h(q0, q1, ck0);
        float d1 = dot8h(q0, q1, ck1);
        float d2 = dot8h(q0, q1, ck2);
        float d3 = dot8h(q0, q1, ck3);
#pragma unroll
        for (int o = 8; o > 0; o >>= 1) {
            d0 += __shfl_xor_sync(0xffffffffu, d0, o);
            d1 += __shfl_xor_sync(0xffffffffu, d1, o);
            d2 += __shfl_xor_sync(0xffffffffu, d2, o);
            d3 += __shfl_xor_sync(0xffffffffu, d3, o);
        }
        d0 *= scale; d1 *= scale; d2 *= scale; d3 *= scale;
        float mx = fmaxf(fmaxf(d0, d1), fmaxf(d2, d3));
        float mn = fmaxf(m, mx);
        float corr = __expf(m - mn);
        float w0 = __expf(d0 - mn), w1 = __expf(d1 - mn);
        float w2 = __expf(d2 - mn), w3 = __expf(d3 - mn);
        ssum = ssum * corr + w0 + w1 + w2 + w3;
#pragma unroll
        for (int j = 0; j < 8; j++) a[j] *= corr;
        acc8h(a, w0, cv0); acc8h(a, w1, cv1);
        acc8h(a, w2, cv2); acc8h(a, w3, cv3);
        m = mn;
    }
    for (; p < end; p++) {
        const __half* kb = &g_kvh[(size_t)g_csr[p] * 512 + base_off];
        uint4 ck = *(const uint4*)kb, cv = *(const uint4*)(kb + 256);
        float d = dot8h(q0, q1, ck);
#pragma unroll
        for (int o = 8; o > 0; o >>= 1) d += __shfl_xor_sync(0xffffffffu, d, o);
        d *= scale;
        float mn = fmaxf(m, d);
        float corr = __expf(m - mn);
        float w = __expf(d - mn);
        ssum = ssum * corr + w;
#pragma unroll
        for (int j = 0; j < 8; j++) a[j] *= corr;
        acc8h(a, w, cv);
        m = mn;
    }

    float inv = 1.f / (ssum + 1e-16f);
#pragma unroll
    for (int j = 0; j < 8; j++) {
        float o = a[j] * inv;
        a[j] = 0.5f * o * (1.f + erff(o * 0.7071067811865475f));
    }
    const int k = hl * 128 + l * 8;
    uint32_t hi[4], lo[4];
    split2(a[0], a[1], hi[0], lo[0]);
    split2(a[2], a[3], hi[1], lo[1]);
    split2(a[4], a[5], hi[2], lo[2]);
    split2(a[6], a[7], hi[3], lo[3]);
    uint32_t* d = (uint32_t*)g_agg_hl + (size_t)dst * 256
                + (k >> 4) * 16 + ((k & 15) >> 1);
    *(uint4*)d       = make_uint4(hi[0], hi[1], hi[2], hi[3]);
    *(uint4*)(d + 8) = make_uint4(lo[0], lo[1], lo[2], lo[3]);
}

__global__ void zin_kernel(const int* __restrict__ nodes,
                           const float* __restrict__ Wdec,
                           const float* __restrict__ bdec)
{
    __shared__ float row[256];
    int r = blockIdx.x, t = threadIdx.x;
    row[t] = g_za[(size_t)nodes[r] * 256 + t];
    __syncthreads();
    float s = bdec[t];
#pragma unroll 8
    for (int k = 0; k < 256; k++) s += row[k] * Wdec[k * 256 + t];
    float s1 = __shfl_xor_sync(0xffffffffu, s, 1);
    if ((t & 1) == 0) {
        uint32_t hi, lo;
        split2(s, s1, hi, lo);
        uint32_t* d = (uint32_t*)g_zin_hl + (size_t)r * 256
                    + (t >> 4) * 16 + ((t & 15) >> 1);
        d[0] = hi; d[8] = lo;
    }
}

static inline GP mkgp(const float* A, int lda, const __nv_bfloat16* Ahl,
                      const __nv_bfloat16* B,
                      float* C, __half* Ch, __nv_bfloat16* Chl, int ldc,
                      const float* bias, int act, int M, int N, int K,
                      const float* aux = nullptr, const float* skipp = nullptr)
{
    GP p; p.A = A; p.lda = lda; p.Ahl = Ahl; p.B = B;
    p.C = C; p.Ch = Ch; p.Chl = Chl; p.ldc = ldc;
    p.bias = bias; p.act = act; p.M = M; p.N = N; p.K = K;
    p.aux = aux; p.skipp = skipp;
    return p;
}

extern "C" void kernel_launch(void* const* d_in, const int* in_sizes, int n_in,
                              void* d_out, int out_size)
{
    const float* x_author    = (const float*)d_in[0];
    const float* x_paper     = (const float*)d_in[1];
    const int*   edge_b_src  = (const int*)d_in[4];
    const int*   edge_b_dst  = (const int*)d_in[5];
    const int*   input_nodes = (const int*)d_in[6];
    const float* W_in_a  = (const float*)d_in[7];
    const float* b_in_a  = (const float*)d_in[8];
    const float* W_in_p  = (const float*)d_in[9];
    const float* b_in_p  = (const float*)d_in[10];
    const float* Wkqv_a  = (const float*)d_in[11];
    const float* bkqv_a  = (const float*)d_in[12];
    const float* Wkqv_p  = (const float*)d_in[13];
    const float* bkqv_p  = (const float*)d_in[14];
    const float* Wk_rel_b = (const float*)d_in[17];
    const float* Wv_rel_b = (const float*)d_in[18];
    const float* p_b     = (const float*)d_in[20];
    const float* Wout_a  = (const float*)d_in[21];
    const float* bout_a  = (const float*)d_in[22];
    const float* skip_a  = (const float*)d_in[25];
    const float* W_dec   = (const float*)d_in[27];
    const float* b_dec   = (const float*)d_in[28];

    const int Na = in_sizes[0] / 128;
    const int Np = in_sizes[1] / 128;
    const int E  = in_sizes[4];
    const int NI = in_sizes[6];

    float *xa, *qa, *za, *bf;
    __half* kvh;
    __nv_bfloat16 *xp_hl, *xa_hl, *agg_hl, *za_hl, *zin_hl;
    __nv_bfloat16 *wft_hl, *winp_hl, *wina_hl, *wq_hl, *wout_hl;
    cudaGetSymbolAddress((void**)&xa,  g_xa);
    cudaGetSymbolAddress((void**)&qa,  g_qa);
    cudaGetSymbolAddress((void**)&kvh, g_kvh);
    cudaGetSymbolAddress((void**)&za,  g_za);
    cudaGetSymbolAddress((void**)&bf,  g_bf);
    cudaGetSymbolAddress((void**)&xp_hl,  g_xp_hl);
    cudaGetSymbolAddress((void**)&xa_hl,  g_xa_hl);
    cudaGetSymbolAddress((void**)&agg_hl, g_agg_hl);
    cudaGetSymbolAddress((void**)&za_hl,  g_za_hl);
    cudaGetSymbolAddress((void**)&zin_hl, g_zin_hl);
    cudaGetSymbolAddress((void**)&wft_hl,  g_wft_hl);
    cudaGetSymbolAddress((void**)&winp_hl, g_winp_hl);
    cudaGetSymbolAddress((void**)&wina_hl, g_wina_hl);
    cudaGetSymbolAddress((void**)&wq_hl,   g_wq_hl);
    cudaGetSymbolAddress((void**)&wout_hl, g_wout_hl);

    fuse_kernel<<<256, 256>>>(Wkqv_p, Wk_rel_b, Wv_rel_b);
    tr_all<<<dim3(8, 8, 4), dim3(32, 8)>>>(W_in_p, W_in_a, Wkqv_a + 256, Wout_a);
    bias_fuse_kernel<<<64, 256>>>(bkqv_p, Wk_rel_b, Wv_rel_b);

    // xp (hl only) & xa (fp32 + hl), A fp32
    {
        GP pxp = mkgp(x_paper,  128, nullptr, winp_hl,
                      nullptr, nullptr, xp_hl, 256, b_in_p, 1, Np, 256, 128);
        GP pxa = mkgp(x_author, 128, nullptr, wina_hl,
                      xa, nullptr, xa_hl, 256, b_in_a, 1, Na, 256, 128);
        int gy = (Na > Np ? Na : Np);
        mm_nt<false><<<dim3(2, (gy + 127) / 128, 2), 256>>>(pxp, pxa);
    }
    // kv (fp16) & qa (fp32), A = hl
    {
        GP pkv = mkgp(nullptr, 0, xp_hl, wft_hl,
                      nullptr, kvh, nullptr, 512, bf, 0, Np, 512, 256);
        GP pqa = mkgp(nullptr, 0, xa_hl, wq_hl,
                      qa, nullptr, nullptr, 256, bkqv_a + 256, 0, Na, 256, 256);
        int gy = (Na > Np ? Na : Np);
        mm_nt<true><<<dim3(4, (gy + 127) / 128, 2), 256>>>(pkv, pqa);
    }
    zero_deg_kernel<<<(Na + 256) / 256, 256>>>(Na);
    hist_kernel<<<(E + 255) / 256, 256>>>(edge_b_dst, E);
    scan_kernel<<<1, 1024>>>(Na);
    scatter_kernel<<<(E + 255) / 256, 256>>>(edge_b_src, edge_b_dst, E);
    {
        int blocks = (Na * 32 + 255) / 256;
        attn_kernel<<<blocks, 256>>>(Na, p_b);
    }
    // za gated residual (fp32 + hl), A = agg_hl
    {
        GP pw = mkgp(nullptr, 0, agg_hl, wout_hl,
                     za, nullptr, za_hl, 256, bout_a, 3, Na, 256, 256, xa, skip_a);
        mm_nt<true><<<dim3(2, (Na + 127) / 128, 1), 256>>>(pw, pw);
    }
    zin_kernel<<<NI, 256>>>(input_nodes, W_dec, b_dec);
    // final: sigmoid(zin @ za_hl^T), A = zin_hl
    {
        GP pf = mkgp(nullptr, 0, zin_hl, za_hl,
                     (float*)d_out, nullptr, nullptr, Na, nullptr, 2, NI, Na, 256);
        mm_nt<true><<<dim3((Na + 127) / 128, (NI + 127) / 128, 1), 256>>>(pf, pf);
    }
}

// round 16
// speedup vs baseline: 1.0161x; 1.0161x over previous
#include <cuda_runtime.h>
#include <cuda_bf16.h>
#include <cuda_fp16.h>
#include <math.h>
#include <stdint.h>

#define MAX_N  50048
#define MAX_E  800000
#define MAX_NI 2048

__device__ float g_xp  [MAX_N * 256];
__device__ float g_xa  [MAX_N * 256];
__device__ float g_qa  [MAX_N * 256];
__device__ __half g_kvh[MAX_N * 512];
__device__ float g_za  [MAX_N * 256];
__device__ float g_bf  [512];
__device__ __nv_bfloat16 g_agg_hl[MAX_N * 512];
__device__ __nv_bfloat16 g_za_hl [MAX_N * 512];
__device__ __nv_bfloat16 g_zin_hl[MAX_NI * 512];
__device__ __nv_bfloat16 g_wft_hl [512 * 512];
__device__ __nv_bfloat16 g_winp_hl[256 * 256];
__device__ __nv_bfloat16 g_wina_hl[256 * 256];
__device__ __nv_bfloat16 g_wq_hl  [256 * 512];
__device__ __nv_bfloat16 g_wout_hl[256 * 512];
__device__ int   g_deg [MAX_N + 1];
__device__ int   g_off [MAX_N + 1];
__device__ int   g_cur [MAX_N];
__device__ int   g_csr [MAX_E];

__device__ __forceinline__ void split2(float f0, float f1,
                                       uint32_t& hi, uint32_t& lo)
{
    uint32_t b0 = __float_as_uint(f0), b1 = __float_as_uint(f1);
    hi = __byte_perm(b0, b1, 0x7632);
    float r0 = f0 - __uint_as_float(b0 & 0xFFFF0000u);
    float r1 = f1 - __uint_as_float(b1 & 0xFFFF0000u);
    __nv_bfloat162 t = __floats2bfloat162_rn(r0, r1);
    lo = *(uint32_t*)&t;
}

__device__ __forceinline__ uint32_t smem_u32(const void* p) {
    uint32_t a;
    asm("{ .reg .u64 t; cvta.to.shared.u64 t, %1; cvt.u32.u64 %0, t; }"
        : "=r"(a) : "l"(p));
    return a;
}

#define LDSM4(r0, r1, r2, r3, addr) \
    asm volatile("ldmatrix.sync.aligned.m8n8.x4.shared.b16 {%0,%1,%2,%3}, [%4];" \
                 : "=r"(r0), "=r"(r1), "=r"(r2), "=r"(r3) : "r"(addr))

#define MMA16816(acc, a0, a1, a2, a3, b0, b1) \
    asm volatile("mma.sync.aligned.m16n8k16.row.col.f32.bf16.bf16.f32 " \
                 "{%0,%1,%2,%3}, {%4,%5,%6,%7}, {%8,%9}, {%0,%1,%2,%3};\n" \
                 : "+f"((acc)[0]), "+f"((acc)[1]), "+f"((acc)[2]), "+f"((acc)[3]) \
                 : "r"(a0), "r"(a1), "r"(a2), "r"(a3), "r"(b0), "r"(b1))

#define CPASYNC16(smem, gptr) \
    asm volatile("cp.async.cg.shared.global [%0], [%1], 16;" \
                 :: "r"(smem), "l"(gptr) : "memory")
#define CPASYNC_COMMIT() asm volatile("cp.async.commit_group;" ::: "memory")
#define CPASYNC_WAIT0()  asm volatile("cp.async.wait_group 0;" ::: "memory")

#define SMSTR 40

struct GP {
    const float* A; int lda;
    const __nv_bfloat16* Ahl;
    const __nv_bfloat16* B;
    float* C; __half* Ch; __nv_bfloat16* Chl;
    int ldc;
    const float* bias; int act;
    int M, N, K;
    int terms;                      // 1 = Ah*Bh only, 3 = full compensated
    const float* aux; const float* skipp;
};

template <bool AHL>
__global__ void __launch_bounds__(256, 2)
mm_nt(GP p0, GP p1)
{
    __shared__ __align__(16) __nv_bfloat16 As[2][128 * SMSTR];
    __shared__ __align__(16) __nv_bfloat16 Bs[2][128 * SMSTR];

    const GP p = (blockIdx.z == 0) ? p0 : p1;
    const int n0 = blockIdx.x * 128;
    const int m0 = blockIdx.y * 128;
    if (n0 >= p.N || m0 >= p.M) return;

    const int tid  = threadIdx.x;
    const int warp = tid >> 5, lane = tid & 31;
    const int gq = lane >> 2, tg = lane & 3;
    const int wm = warp >> 1, wn = warp & 1;
    const int l15 = lane & 15, l16 = lane >> 4;
    const bool full = (p.terms == 3);

    float acc[2][8][4];
#pragma unroll
    for (int i = 0; i < 2; i++)
#pragma unroll
        for (int j = 0; j < 8; j++)
#pragma unroll
            for (int e = 0; e < 4; e++) acc[i][j][e] = 0.f;

    const int srow = tid >> 1, shalf = tid & 1;
    const float4 z4 = make_float4(0.f, 0.f, 0.f, 0.f);
    const int KT = p.K >> 4;
    const int twoK = 2 * p.K;

    const uint4* bp = (const uint4*)(p.B + (size_t)(n0 + srow) * twoK + shalf * 16);
    const uint32_t bdst0 = smem_u32(&Bs[0][srow * SMSTR + shalf * 16]);
    const uint32_t bdst1 = smem_u32(&Bs[1][srow * SMSTR + shalf * 16]);
    const uint32_t adst0 = smem_u32(&As[0][srow * SMSTR + shalf * 16]);
    const uint32_t adst1 = smem_u32(&As[1][srow * SMSTR + shalf * 16]);

    const bool aok = srow < ((p.M - m0 > 128) ? 128 : (p.M - m0));
    const float* ap = AHL ? nullptr
                          : p.A + (size_t)(m0 + srow) * p.lda + shalf * 8;
    const uint4* aphl = AHL
        ? (const uint4*)(p.Ahl + (size_t)(m0 + srow) * twoK + shalf * 16)
        : nullptr;

    float4 ra0, ra1;

    if (AHL) {
        CPASYNC16(adst0,      aphl);
        CPASYNC16(adst0 + 16, aphl + 1);
        CPASYNC16(bdst0,      bp);
        CPASYNC16(bdst0 + 16, bp + 1);
        CPASYNC_COMMIT();
    } else {
        CPASYNC16(bdst0,      bp);
        CPASYNC16(bdst0 + 16, bp + 1);
        CPASYNC_COMMIT();
        ra0 = aok ? *(const float4*)(ap + 0) : z4;
        ra1 = aok ? *(const float4*)(ap + 4) : z4;
        uint32_t h[4], l[4];
        split2(ra0.x, ra0.y, h[0], l[0]); split2(ra0.z, ra0.w, h[1], l[1]);
        split2(ra1.x, ra1.y, h[2], l[2]); split2(ra1.z, ra1.w, h[3], l[3]);
        uint4* ah = (uint4*)&As[0][srow * SMSTR + shalf * 8];
        ah[0] = make_uint4(h[0], h[1], h[2], h[3]);
        ah[2] = make_uint4(l[0], l[1], l[2], l[3]);
    }
    CPASYNC_WAIT0();
    __syncthreads();

    for (int kt = 0; kt < KT; kt++) {
        const int cur = kt & 1;
        const bool more = (kt + 1 < KT);
        if (more) {
            uint32_t bd = (cur ? bdst0 : bdst1);
            const uint4* b2 = bp + (kt + 1) * 4;
            CPASYNC16(bd,      b2);
            CPASYNC16(bd + 16, b2 + 1);
            if (AHL) {
                uint32_t ad = (cur ? adst0 : adst1);
                const uint4* a2 = aphl + (kt + 1) * 4;
                CPASYNC16(ad,      a2);
                CPASYNC16(ad + 16, a2 + 1);
            } else {
                const float* a2 = ap + (kt + 1) * 16;
                ra0 = aok ? *(const float4*)(a2 + 0) : z4;
                ra1 = aok ? *(const float4*)(a2 + 4) : z4;
            }
            CPASYNC_COMMIT();
        }

        const uint32_t asb = smem_u32(&As[cur][0]);
        const uint32_t bsb = smem_u32(&Bs[cur][0]);

        uint32_t ahf[2][4], alf[2][4];
#pragma unroll
        for (int mt = 0; mt < 2; mt++) {
            int row = wm * 32 + mt * 16 + l15;
            uint32_t a_ad = asb + row * (SMSTR * 2) + l16 * 16;
            LDSM4(ahf[mt][0], ahf[mt][1], ahf[mt][2], ahf[mt][3], a_ad);
            if (full)
                LDSM4(alf[mt][0], alf[mt][1], alf[mt][2], alf[mt][3], a_ad + 32);
        }
#pragma unroll
        for (int npp = 0; npp < 2; npp++) {
            uint32_t bhf[2][4], blf[2][4];
#pragma unroll
            for (int q = 0; q < 2; q++) {
                int row = wn * 64 + (npp * 2 + q) * 16 + l15;
                uint32_t b_ad = bsb + row * (SMSTR * 2) + l16 * 16;
                LDSM4(bhf[q][0], bhf[q][1], bhf[q][2], bhf[q][3], b_ad);
                if (full)
                    LDSM4(blf[q][0], blf[q][1], blf[q][2], blf[q][3], b_ad + 32);
            }
#pragma unroll
            for (int q = 0; q < 2; q++)
#pragma unroll
                for (int mt = 0; mt < 2; mt++)
#pragma unroll
                    for (int j = 0; j < 2; j++)
                        MMA16816(acc[mt][(npp * 2 + q) * 2 + j],
                                 ahf[mt][0], ahf[mt][1], ahf[mt][2], ahf[mt][3],
                                 bhf[q][j], bhf[q][2 + j]);
            if (full) {
#pragma unroll
                for (int q = 0; q < 2; q++)
#pragma unroll
                    for (int mt = 0; mt < 2; mt++)
#pragma unroll
                        for (int j = 0; j < 2; j++)
                            MMA16816(acc[mt][(npp * 2 + q) * 2 + j],
                                     ahf[mt][0], ahf[mt][1], ahf[mt][2], ahf[mt][3],
                                     blf[q][j], blf[q][2 + j]);
#pragma unroll
                for (int q = 0; q < 2; q++)
#pragma unroll
                    for (int mt = 0; mt < 2; mt++)
#pragma unroll
                        for (int j = 0; j < 2; j++)
                            MMA16816(acc[mt][(npp * 2 + q) * 2 + j],
                                     alf[mt][0], alf[mt][1], alf[mt][2], alf[mt][3],
                                     bhf[q][j], bhf[q][2 + j]);
            }
        }

        if (more) {
            if (!AHL) {
                const int nxt = 1 - cur;
                uint32_t h[4], l[4];
                split2(ra0.x, ra0.y, h[0], l[0]); split2(ra0.z, ra0.w, h[1], l[1]);
                split2(ra1.x, ra1.y, h[2], l[2]); split2(ra1.z, ra1.w, h[3], l[3]);
                uint4* ah = (uint4*)&As[nxt][srow * SMSTR + shalf * 8];
                ah[0] = make_uint4(h[0], h[1], h[2], h[3]);
                ah[2] = make_uint4(l[0], l[1], l[2], l[3]);
            }
            CPASYNC_WAIT0();
            __syncthreads();
        }
    }

    float ga = 0.f;
    if (p.act == 3) ga = 1.f / (1.f + __expf(-p.skipp[0]));
    const int hlstride = 256;     // hl rows: 512 bf16 = 256 u32 (K=256 consumers)

#pragma unroll
    for (int mt = 0; mt < 2; mt++) {
#pragma unroll
        for (int nt = 0; nt < 8; nt++) {
            int r0 = m0 + wm * 32 + mt * 16 + gq;
            int cc = n0 + wn * 64 + nt * 8 + 2 * tg;
            if (cc < p.N) {
                float b0 = p.bias ? p.bias[cc] : 0.f;
                float b1 = p.bias ? p.bias[cc + 1] : 0.f;
                float v0 = acc[mt][nt][0] + b0, v1 = acc[mt][nt][1] + b1;
                float v2 = acc[mt][nt][2] + b0, v3 = acc[mt][nt][3] + b1;
                if (p.act == 1) {
                    v0 = fmaxf(v0, 0.f); v1 = fmaxf(v1, 0.f);
                    v2 = fmaxf(v2, 0.f); v3 = fmaxf(v3, 0.f);
                } else if (p.act == 2) {
                    v0 = 1.f / (1.f + __expf(-v0)); v1 = 1.f / (1.f + __expf(-v1));
                    v2 = 1.f / (1.f + __expf(-v2)); v3 = 1.f / (1.f + __expf(-v3));
                } else if (p.act == 3) {
                    if (r0 < p.M) {
                        v0 = ga * v0 + (1.f - ga) * p.aux[(size_t)r0 * 256 + cc];
                        v1 = ga * v1 + (1.f - ga) * p.aux[(size_t)r0 * 256 + cc + 1];
                    }
                    if (r0 + 8 < p.M) {
                        v2 = ga * v2 + (1.f - ga) * p.aux[(size_t)(r0 + 8) * 256 + cc];
                        v3 = ga * v3 + (1.f - ga) * p.aux[(size_t)(r0 + 8) * 256 + cc + 1];
                    }
                }
                if (p.Ch) {
                    __half2* Ch = (__half2*)p.Ch;
                    if (r0 < p.M)
                        Ch[((size_t)r0 * p.ldc + cc) >> 1] = __floats2half2_rn(v0, v1);
                    if (r0 + 8 < p.M)
                        Ch[((size_t)(r0 + 8) * p.ldc + cc) >> 1] = __floats2half2_rn(v2, v3);
                }
                if (p.C) {
                    if (r0 < p.M) {
                        float2 q = {v0, v1};
                        *(float2*)&p.C[(size_t)r0 * p.ldc + cc] = q;
                    }
                    if (r0 + 8 < p.M) {
                        float2 q = {v2, v3};
                        *(float2*)&p.C[(size_t)(r0 + 8) * p.ldc + cc] = q;
                    }
                }
                if (p.Chl) {
                    int coff = (cc >> 4) * 16 + ((cc & 15) >> 1);
                    if (r0 < p.M) {
                        uint32_t hi, lo;
                        split2(v0, v1, hi, lo);
                        uint32_t* d = (uint32_t*)p.Chl + (size_t)r0 * hlstride + coff;
                        d[0] = hi; d[8] = lo;
                    }
                    if (r0 + 8 < p.M) {
                        uint32_t hi, lo;
                        split2(v2, v3, hi, lo);
                        uint32_t* d = (uint32_t*)p.Chl + (size_t)(r0 + 8) * hlstride + coff;
                        d[0] = hi; d[8] = lo;
                    }
                }
            }
        }
    }
}

__global__ void tr_all(const float* __restrict__ Wp, const float* __restrict__ Wa,
                       const float* __restrict__ Wq, const float* __restrict__ Wo)
{
    __shared__ float t[32][33];
    const float* in; __nv_bfloat16* out; int ldin, K, N;
    switch (blockIdx.z) {
        case 0: in = Wp; out = g_winp_hl; ldin = 256; K = 128; N = 256; break;
        case 1: in = Wa; out = g_wina_hl; ldin = 256; K = 128; N = 256; break;
        case 2: in = Wq; out = g_wq_hl;   ldin = 768; K = 256; N = 256; break;
        default: in = Wo; out = g_wout_hl; ldin = 256; K = 256; N = 256; break;
    }
    int bx = blockIdx.x * 32, by = blockIdx.y * 32;
    if (bx >= N || by >= K) return;
    int x = bx + threadIdx.x;
    for (int dy = 0; dy < 32; dy += 8) {
        int y = by + threadIdx.y + dy;
        if (x < N && y < K) t[threadIdx.y + dy][threadIdx.x] = in[(size_t)y * ldin + x];
    }
    __syncthreads();
    if (threadIdx.x < 16) {
        for (int dy = 0; dy < 32; dy += 8) {
            int n_ = bx + threadIdx.y + dy;
            int k0 = by + 2 * threadIdx.x;
            if (n_ < N && k0 < K) {
                float f0 = t[2 * threadIdx.x][threadIdx.y + dy];
                float f1 = t[2 * threadIdx.x + 1][threadIdx.y + dy];
                uint32_t hi, lo;
                split2(f0, f1, hi, lo);
                uint32_t* d = (uint32_t*)(out + (size_t)n_ * 2 * K
                                          + (k0 >> 4) * 32 + (k0 & 15));
                d[0] = hi; d[8] = lo;
            }
        }
    }
}

__global__ void fuse_kernel(const float* __restrict__ Wkqv_p,
                            const float* __restrict__ Rk,
                            const float* __restrict__ Rv)
{
    int idx = blockIdx.x * 256 + threadIdx.x;
    int c = idx >> 7;
    int j = idx & 127;
    int isv = c >> 8, h = (c >> 7) & 1, e = c & 127;
    const float* R = (isv ? Rv : Rk) + h * 16384;
    const float* w0 = Wkqv_p + (size_t)(2 * j) * 768 + (isv ? 512 : 0) + h * 128;
    const float* w1 = w0 + 768;
    float s0 = 0.f, s1 = 0.f;
#pragma unroll 8
    for (int d = 0; d < 128; d++) {
        float rv = R[d * 128 + e];
        s0 += w0[d] * rv;
        s1 += w1[d] * rv;
    }
    uint32_t hi, lo;
    split2(s0, s1, hi, lo);
    int k = 2 * j;
    uint32_t* dst = (uint32_t*)(g_wft_hl + (size_t)c * 512 + (k >> 4) * 32 + (k & 15));
    dst[0] = hi; dst[8] = lo;
}

__global__ void bias_fuse_kernel(const float* __restrict__ bkqv,
                                 const float* __restrict__ Rk,
                                 const float* __restrict__ Rv)
{
    int gw = (blockIdx.x * 256 + threadIdx.x) >> 5;
    int lane = threadIdx.x & 31;
    if (gw >= 512) return;
    int isv = gw >> 8, h = (gw >> 7) & 1, e = gw & 127;
    const float* R = (isv ? Rv : Rk) + h * 16384;
    const float* b = bkqv + (isv ? 512 : 0) + h * 128;
    float s = 0.f;
#pragma unroll
    for (int i = 0; i < 4; i++) {
        int d = lane + 32 * i;
        s += b[d] * R[d * 128 + e];
    }
#pragma unroll
    for (int o = 16; o > 0; o >>= 1) s += __shfl_xor_sync(0xffffffffu, s, o);
    if (lane == 0) g_bf[gw] = s;
}

__global__ void zero_deg_kernel(int n)
{
    int i = blockIdx.x * blockDim.x + threadIdx.x;
    if (i <= n) g_deg[i] = 0;
}
__global__ void hist_kernel(const int* __restrict__ dst, int E)
{
    int e = blockIdx.x * blockDim.x + threadIdx.x;
    if (e < E) atomicAdd(&g_deg[dst[e]], 1);
}
__global__ void __launch_bounds__(1024) scan_kernel(int n)
{
    __shared__ int part[1024];
    int t = threadIdx.x;
    int chunk = (n + 1023) >> 10;
    int b = t * chunk, e = min(b + chunk, n);
    int s = 0;
    for (int i = b; i < e; i++) s += g_deg[i];
    part[t] = s;
    __syncthreads();
    for (int o = 1; o < 1024; o <<= 1) {
        int v = (t >= o) ? part[t - o] : 0;
        __syncthreads();
        part[t] += v;
        __syncthreads();
    }
    int run = (t == 0) ? 0 : part[t - 1];
    for (int i = b; i < e; i++) {
        g_off[i] = run; g_cur[i] = run; run += g_deg[i];
    }
    if (t == 0) g_off[n] = part[1023];
}
__global__ void scatter_kernel(const int* __restrict__ src,
                               const int* __restrict__ dst, int E)
{
    int e = blockIdx.x * blockDim.x + threadIdx.x;
    if (e < E) {
        int p = atomicAdd(&g_cur[dst[e]], 1);
        g_csr[p] = src[e];
    }
}

__device__ __forceinline__ float dot8h(const float4& q0, const float4& q1,
                                       const uint4& ck)
{
    float2 k0 = __half22float2(*(const __half2*)&ck.x);
    float2 k1 = __half22float2(*(const __half2*)&ck.y);
    float2 k2 = __half22float2(*(const __half2*)&ck.z);
    float2 k3 = __half22float2(*(const __half2*)&ck.w);
    return q0.x * k0.x + q0.y * k0.y + q0.z * k1.x + q0.w * k1.y
         + q1.x * k2.x + q1.y * k2.y + q1.z * k3.x + q1.w * k3.y;
}

__device__ __forceinline__ void acc8h(float (&a)[8], float w, const uint4& cv)
{
    float2 v0 = __half22float2(*(const __half2*)&cv.x);
    float2 v1 = __half22float2(*(const __half2*)&cv.y);
    float2 v2 = __half22float2(*(const __half2*)&cv.z);
    float2 v3 = __half22float2(*(const __half2*)&cv.w);
    a[0] += w * v0.x; a[1] += w * v0.y;
    a[2] += w * v1.x; a[3] += w * v1.y;
    a[4] += w * v2.x; a[5] += w * v2.y;
    a[6] += w * v3.x; a[7] += w * v3.y;
}

__global__ void attn_kernel(int Na, const float* __restrict__ p_rel)
{
    int gw = (blockIdx.x * 256 + threadIdx.x) >> 5;
    int lane = threadIdx.x & 31;
    if (gw >= Na) return;
    const int dst = gw;
    const int hl = lane >> 4;
    const int l  = lane & 15;

    const int beg = g_off[dst], end = g_off[dst + 1];
    const float scale = p_rel[hl] * 0.08838834764831845f;

    const float* qb = &g_qa[(size_t)dst * 256 + hl * 128 + l * 8];
    const float4 q0 = *(const float4*)qb;
    const float4 q1 = *(const float4*)(qb + 4);

    float m = -INFINITY, ssum = 0.f;
    float a[8] = {0.f, 0.f, 0.f, 0.f, 0.f, 0.f, 0.f, 0.f};

    const size_t base_off = (size_t)hl * 128 + l * 8;

    int p = beg;
    for (; p + 4 <= end; p += 4) {
        const __half* kb0 = &g_kvh[(size_t)g_csr[p]     * 512 + base_off];
        const __half* kb1 = &g_kvh[(size_t)g_csr[p + 1] * 512 + base_off];
        const __half* kb2 = &g_kvh[(size_t)g_csr[p + 2] * 512 + base_off];
        const __half* kb3 = &g_kvh[(size_t)g_csr[p + 3] * 512 + base_off];
        uint4 ck0 = *(const uint4*)kb0, cv0 = *(const uint4*)(kb0 + 256);
        uint4 ck1 = *(const uint4*)kb1, cv1 = *(const uint4*)(kb1 + 256);
        uint4 ck2 = *(const uint4*)kb2, cv2 = *(const uint4*)(kb2 + 256);
        uint4 ck3 = *(const uint4*)kb3, cv3 = *(const uint4*)(kb3 + 256);

        float d0 = dot8h(q0, q1, ck0);
        float d1 = dot8h(q0, q1, ck1);
        float d2 = dot8h(q0, q1, ck2);
        float d3 = dot8h(q0, q1, ck3);
#pragma unroll
        for (int o = 8; o > 0; o >>= 1) {
            d0 += __shfl_xor_sync(0xffffffffu, d0, o);
            d1 += __shfl_xor_sync(0xffffffffu, d1, o);
            d2 += __shfl_xor_sync(0xffffffffu, d2, o);
            d3 += __shfl_xor_sync(0xffffffffu, d3, o);
        }
        d0 *= scale; d1 *= scale; d2 *= scale; d3 *= scale;
        float mx = fmaxf(fmaxf(d0, d1), fmaxf(d2, d3));
        float mn = fmaxf(m, mx);
        float corr = __expf(m - mn);
        float w0 = __expf(d0 - mn), w1 = __expf(d1 - mn);
        float w2 = __expf(d2 - mn), w3 = __expf(d3 - mn);
        ssum = ssum * corr + w0 + w1 + w2 + w3;
#pragma unroll
        for (int j = 0; j < 8; j++) a[j] *= corr;
        acc8h(a, w0, cv0); acc8h(a, w1, cv1);
        acc8h(a, w2, cv2); acc8h(a, w3, cv3);
        m = mn;
    }
    for (; p < end; p++) {
        const __half* kb = &g_kvh[(size_t)g_csr[p] * 512 + base_off];
        uint4 ck = *(const uint4*)kb, cv = *(const uint4*)(kb + 256);
        float d = dot8h(q0, q1, ck);
#pragma unroll
        for (int o = 8; o > 0; o >>= 1) d += __shfl_xor_sync(0xffffffffu, d, o);
        d *= scale;
        float mn = fmaxf(m, d);
        float corr = __expf(m - mn);
        float w = __expf(d - mn);
        ssum = ssum * corr + w;
#pragma unroll
        for (int j = 0; j < 8; j++) a[j] *= corr;
        acc8h(a, w, cv);
        m = mn;
    }

    float inv = 1.f / (ssum + 1e-16f);
#pragma unroll
    for (int j = 0; j < 8; j++) {
        float o = a[j] * inv;
        a[j] = 0.5f * o * (1.f + erff(o * 0.7071067811865475f));
    }
    const int k = hl * 128 + l * 8;
    uint32_t hi[4], lo[4];
    split2(a[0], a[1], hi[0], lo[0]);
    split2(a[2], a[3], hi[1], lo[1]);
    split2(a[4], a[5], hi[2], lo[2]);
    split2(a[6], a[7], hi[3], lo[3]);
    uint32_t* d = (uint32_t*)g_agg_hl + (size_t)dst * 256
                + (k >> 4) * 16 + ((k & 15) >> 1);
    *(uint4*)d       = make_uint4(hi[0], hi[1], hi[2], hi[3]);
    *(uint4*)(d + 8) = make_uint4(lo[0], lo[1], lo[2], lo[3]);
}

__global__ void zin_kernel(const int* __restrict__ nodes,
                           const float* __restrict__ Wdec,
                           const float* __restrict__ bdec)
{
    __shared__ float row[256];
    int r = blockIdx.x, t = threadIdx.x;
    row[t] = g_za[(size_t)nodes[r] * 256 + t];
    __syncthreads();
    float s = bdec[t];
#pragma unroll 8
    for (int k = 0; k < 256; k++) s += row[k] * Wdec[k * 256 + t];
    float s1 = __shfl_xor_sync(0xffffffffu, s, 1);
    if ((t & 1) == 0) {
        uint32_t hi, lo;
        split2(s, s1, hi, lo);
        uint32_t* d = (uint32_t*)g_zin_hl + (size_t)r * 256
                    + (t >> 4) * 16 + ((t & 15) >> 1);
        d[0] = hi; d[8] = lo;
    }
}

static inline GP mkgp(const float* A, int lda, const __nv_bfloat16* Ahl,
                      const __nv_bfloat16* B,
                      float* C, __half* Ch, __nv_bfloat16* Chl, int ldc,
                      const float* bias, int act, int M, int N, int K, int terms,
                      const float* aux = nullptr, const float* skipp = nullptr)
{
    GP p; p.A = A; p.lda = lda; p.Ahl = Ahl; p.B = B;
    p.C = C; p.Ch = Ch; p.Chl = Chl; p.ldc = ldc;
    p.bias = bias; p.act = act; p.M = M; p.N = N; p.K = K; p.terms = terms;
    p.aux = aux; p.skipp = skipp;
    return p;
}

extern "C" void kernel_launch(void* const* d_in, const int* in_sizes, int n_in,
                              void* d_out, int out_size)
{
    const float* x_author    = (const float*)d_in[0];
    const float* x_paper     = (const float*)d_in[1];
    const int*   edge_b_src  = (const int*)d_in[4];
    const int*   edge_b_dst  = (const int*)d_in[5];
    const int*   input_nodes = (const int*)d_in[6];
    const float* W_in_a  = (const float*)d_in[7];
    const float* b_in_a  = (const float*)d_in[8];
    const float* W_in_p  = (const float*)d_in[9];
    const float* b_in_p  = (const float*)d_in[10];
    const float* Wkqv_a  = (const float*)d_in[11];
    const float* bkqv_a  = (const float*)d_in[12];
    const float* Wkqv_p  = (const float*)d_in[13];
    const float* bkqv_p  = (const float*)d_in[14];
    const float* Wk_rel_b = (const float*)d_in[17];
    const float* Wv_rel_b = (const float*)d_in[18];
    const float* p_b     = (const float*)d_in[20];
    const float* Wout_a  = (const float*)d_in[21];
    const float* bout_a  = (const float*)d_in[22];
    const float* skip_a  = (const float*)d_in[25];
    const float* W_dec   = (const float*)d_in[27];
    const float* b_dec   = (const float*)d_in[28];

    const int Na = in_sizes[0] / 128;
    const int Np = in_sizes[1] / 128;
    const int E  = in_sizes[4];
    const int NI = in_sizes[6];

    float *xp, *xa, *qa, *za, *bf;
    __half* kvh;
    __nv_bfloat16 *agg_hl, *za_hl, *zin_hl;
    __nv_bfloat16 *wft_hl, *winp_hl, *wina_hl, *wq_hl, *wout_hl;
    cudaGetSymbolAddress((void**)&xp,  g_xp);
    cudaGetSymbolAddress((void**)&xa,  g_xa);
    cudaGetSymbolAddress((void**)&qa,  g_qa);
    cudaGetSymbolAddress((void**)&kvh, g_kvh);
    cudaGetSymbolAddress((void**)&za,  g_za);
    cudaGetSymbolAddress((void**)&bf,  g_bf);
    cudaGetSymbolAddress((void**)&agg_hl, g_agg_hl);
    cudaGetSymbolAddress((void**)&za_hl,  g_za_hl);
    cudaGetSymbolAddress((void**)&zin_hl, g_zin_hl);
    cudaGetSymbolAddress((void**)&wft_hl,  g_wft_hl);
    cudaGetSymbolAddress((void**)&winp_hl, g_winp_hl);
    cudaGetSymbolAddress((void**)&wina_hl, g_wina_hl);
    cudaGetSymbolAddress((void**)&wq_hl,   g_wq_hl);
    cudaGetSymbolAddress((void**)&wout_hl, g_wout_hl);

    fuse_kernel<<<256, 256>>>(Wkqv_p, Wk_rel_b, Wv_rel_b);
    tr_all<<<dim3(8, 8, 4), dim3(32, 8)>>>(W_in_p, W_in_a, Wkqv_a + 256, Wout_a);
    bias_fuse_kernel<<<64, 256>>>(bkqv_p, Wk_rel_b, Wv_rel_b);

    // batch1: xp & xa, fp32 A + fp32 out only
    {
        GP pxp = mkgp(x_paper,  128, nullptr, winp_hl,
                      xp, nullptr, nullptr, 256, b_in_p, 1, Np, 256, 128, 3);
        GP pxa = mkgp(x_author, 128, nullptr, wina_hl,
                      xa, nullptr, nullptr, 256, b_in_a, 1, Na, 256, 128, 3);
        int gy = (Na > Np ? Na : Np);
        mm_nt<false><<<dim3(2, (gy + 127) / 128, 2), 256>>>(pxp, pxa);
    }
    // batch2: kv (fp16 out, 3-term) & qa (fp32 out, 3-term)
    {
        GP pkv = mkgp(xp, 256, nullptr, wft_hl,
                      nullptr, kvh, nullptr, 512, bf, 0, Np, 512, 256, 3);
        GP pqa = mkgp(xa, 256, nullptr, wq_hl,
                      qa, nullptr, nullptr, 256, bkqv_a + 256, 0, Na, 256, 256, 3);
        int gy = (Na > Np ? Na : Np);
        mm_nt<false><<<dim3(4, (gy + 127) / 128, 2), 256>>>(pkv, pqa);
    }
    zero_deg_kernel<<<(Na + 256) / 256, 256>>>(Na);
    hist_kernel<<<(E + 255) / 256, 256>>>(edge_b_dst, E);
    scan_kernel<<<1, 1024>>>(Na);
    scatter_kernel<<<(E + 255) / 256, 256>>>(edge_b_src, edge_b_dst, E);
    {
        int blocks = (Na * 32 + 255) / 256;
        attn_kernel<<<blocks, 256>>>(Na, p_b);
    }
    // za gated residual: A = agg_hl, fp32 + hl out (cvt fused)
    {
        GP pw = mkgp(nullptr, 0, agg_hl, wout_hl,
                     za, nullptr, za_hl, 256, bout_a, 3, Na, 256, 256, 3,
                     xa, skip_a);
        mm_nt<true><<<dim3(2, (Na + 127) / 128, 1), 256>>>(pw, pw);
    }
    zin_kernel<<<NI, 256>>>(input_nodes, W_dec, b_dec);
    // final: sigmoid(zin @ za_hl^T), A = zin_hl
    {
        GP pf = mkgp(nullptr, 0, zin_hl, za_hl,
                     (float*)d_out, nullptr, nullptr, Na, nullptr, 2,
                     NI, Na, 256, 3);
        mm_nt<true><<<dim3((Na + 127) / 128, (NI + 127) / 128, 1), 256>>>(pf, pf);
    }
}

// round 17
// speedup vs baseline: 1.0432x; 1.0267x over previous
#include <cuda_runtime.h>
#include <cuda_bf16.h>
#include <cuda_fp16.h>
#include <math.h>
#include <stdint.h>

#define MAX_N  50048
#define MAX_E  800000
#define MAX_NI 2048

__device__ float g_xp  [MAX_N * 256];
__device__ float g_xa  [MAX_N * 256];
__device__ __half g_qah[MAX_N * 256];
__device__ __half g_kvh[MAX_N * 512];
__device__ float g_bf  [512];
__device__ __nv_bfloat16 g_agg_hl[MAX_N * 512];
__device__ __nv_bfloat16 g_za_hl [MAX_N * 512];
__device__ __nv_bfloat16 g_zin_hl[MAX_NI * 512];
__device__ __nv_bfloat16 g_wft_hl [512 * 512];
__device__ __nv_bfloat16 g_winp_hl[256 * 256];
__device__ __nv_bfloat16 g_wina_hl[256 * 256];
__device__ __nv_bfloat16 g_wq_hl  [256 * 512];
__device__ __nv_bfloat16 g_wout_hl[256 * 512];
__device__ int   g_deg [MAX_N + 1];
__device__ int   g_off [MAX_N + 1];
__device__ int   g_cur [MAX_N];
__device__ int   g_csr [MAX_E];

__device__ __forceinline__ void split2(float f0, float f1,
                                       uint32_t& hi, uint32_t& lo)
{
    uint32_t b0 = __float_as_uint(f0), b1 = __float_as_uint(f1);
    hi = __byte_perm(b0, b1, 0x7632);
    float r0 = f0 - __uint_as_float(b0 & 0xFFFF0000u);
    float r1 = f1 - __uint_as_float(b1 & 0xFFFF0000u);
    __nv_bfloat162 t = __floats2bfloat162_rn(r0, r1);
    lo = *(uint32_t*)&t;
}

__device__ __forceinline__ uint32_t smem_u32(const void* p) {
    uint32_t a;
    asm("{ .reg .u64 t; cvta.to.shared.u64 t, %1; cvt.u32.u64 %0, t; }"
        : "=r"(a) : "l"(p));
    return a;
}

#define LDSM4(r0, r1, r2, r3, addr) \
    asm volatile("ldmatrix.sync.aligned.m8n8.x4.shared.b16 {%0,%1,%2,%3}, [%4];" \
                 : "=r"(r0), "=r"(r1), "=r"(r2), "=r"(r3) : "r"(addr))

#define MMA16816(acc, a0, a1, a2, a3, b0, b1) \
    asm volatile("mma.sync.aligned.m16n8k16.row.col.f32.bf16.bf16.f32 " \
                 "{%0,%1,%2,%3}, {%4,%5,%6,%7}, {%8,%9}, {%0,%1,%2,%3};\n" \
                 : "+f"((acc)[0]), "+f"((acc)[1]), "+f"((acc)[2]), "+f"((acc)[3]) \
                 : "r"(a0), "r"(a1), "r"(a2), "r"(a3), "r"(b0), "r"(b1))

#define CPASYNC16(smem, gptr) \
    asm volatile("cp.async.cg.shared.global [%0], [%1], 16;" \
                 :: "r"(smem), "l"(gptr) : "memory")
#define CPASYNC_COMMIT() asm volatile("cp.async.commit_group;" ::: "memory")
#define CPASYNC_WAIT0()  asm volatile("cp.async.wait_group 0;" ::: "memory")

#define SMSTR 40

struct GP {
    const float* A; int lda;
    const __nv_bfloat16* Ahl;
    const __nv_bfloat16* B;
    float* C; __half* Ch; __nv_bfloat16* Chl;
    int ldc;
    const float* bias; int act;
    int M, N, K;
    int terms;
    const float* aux; const float* skipp;
};

template <bool AHL>
__global__ void __launch_bounds__(256, 2)
mm_nt(GP p0, GP p1)
{
    __shared__ __align__(16) __nv_bfloat16 As[2][128 * SMSTR];
    __shared__ __align__(16) __nv_bfloat16 Bs[2][128 * SMSTR];

    const GP p = (blockIdx.z == 0) ? p0 : p1;
    const int n0 = blockIdx.x * 128;
    const int m0 = blockIdx.y * 128;
    if (n0 >= p.N || m0 >= p.M) return;

    const int tid  = threadIdx.x;
    const int warp = tid >> 5, lane = tid & 31;
    const int gq = lane >> 2, tg = lane & 3;
    const int wm = warp >> 1, wn = warp & 1;
    const int l15 = lane & 15, l16 = lane >> 4;
    const bool full = (p.terms == 3);

    float acc[2][8][4];
#pragma unroll
    for (int i = 0; i < 2; i++)
#pragma unroll
        for (int j = 0; j < 8; j++)
#pragma unroll
            for (int e = 0; e < 4; e++) acc[i][j][e] = 0.f;

    const int srow = tid >> 1, shalf = tid & 1;
    const float4 z4 = make_float4(0.f, 0.f, 0.f, 0.f);
    const int KT = p.K >> 4;
    const int twoK = 2 * p.K;

    const uint4* bp = (const uint4*)(p.B + (size_t)(n0 + srow) * twoK + shalf * 16);
    const uint32_t bdst0 = smem_u32(&Bs[0][srow * SMSTR + shalf * 16]);
    const uint32_t bdst1 = smem_u32(&Bs[1][srow * SMSTR + shalf * 16]);
    const uint32_t adst0 = smem_u32(&As[0][srow * SMSTR + shalf * 16]);
    const uint32_t adst1 = smem_u32(&As[1][srow * SMSTR + shalf * 16]);

    const bool aok = srow < ((p.M - m0 > 128) ? 128 : (p.M - m0));
    const float* ap = AHL ? nullptr
                          : p.A + (size_t)(m0 + srow) * p.lda + shalf * 8;
    const uint4* aphl = AHL
        ? (const uint4*)(p.Ahl + (size_t)(m0 + srow) * twoK + shalf * 16)
        : nullptr;

    float4 ra0, ra1;

    if (AHL) {
        CPASYNC16(adst0,      aphl);
        CPASYNC16(adst0 + 16, aphl + 1);
        CPASYNC16(bdst0,      bp);
        CPASYNC16(bdst0 + 16, bp + 1);
        CPASYNC_COMMIT();
    } else {
        CPASYNC16(bdst0,      bp);
        CPASYNC16(bdst0 + 16, bp + 1);
        CPASYNC_COMMIT();
        ra0 = aok ? *(const float4*)(ap + 0) : z4;
        ra1 = aok ? *(const float4*)(ap + 4) : z4;
        uint32_t h[4], l[4];
        split2(ra0.x, ra0.y, h[0], l[0]); split2(ra0.z, ra0.w, h[1], l[1]);
        split2(ra1.x, ra1.y, h[2], l[2]); split2(ra1.z, ra1.w, h[3], l[3]);
        uint4* ah = (uint4*)&As[0][srow * SMSTR + shalf * 8];
        ah[0] = make_uint4(h[0], h[1], h[2], h[3]);
        ah[2] = make_uint4(l[0], l[1], l[2], l[3]);
    }
    CPASYNC_WAIT0();
    __syncthreads();

    for (int kt = 0; kt < KT; kt++) {
        const int cur = kt & 1;
        const bool more = (kt + 1 < KT);
        if (more) {
            uint32_t bd = (cur ? bdst0 : bdst1);
            const uint4* b2 = bp + (kt + 1) * 4;
            CPASYNC16(bd,      b2);
            CPASYNC16(bd + 16, b2 + 1);
            if (AHL) {
                uint32_t ad = (cur ? adst0 : adst1);
                const uint4* a2 = aphl + (kt + 1) * 4;
                CPASYNC16(ad,      a2);
                CPASYNC16(ad + 16, a2 + 1);
            } else {
                const float* a2 = ap + (kt + 1) * 16;
                ra0 = aok ? *(const float4*)(a2 + 0) : z4;
                ra1 = aok ? *(const float4*)(a2 + 4) : z4;
            }
            CPASYNC_COMMIT();
        }

        const uint32_t asb = smem_u32(&As[cur][0]);
        const uint32_t bsb = smem_u32(&Bs[cur][0]);

        uint32_t ahf[2][4], alf[2][4];
#pragma unroll
        for (int mt = 0; mt < 2; mt++) {
            int row = wm * 32 + mt * 16 + l15;
            uint32_t a_ad = asb + row * (SMSTR * 2) + l16 * 16;
            LDSM4(ahf[mt][0], ahf[mt][1], ahf[mt][2], ahf[mt][3], a_ad);
            if (full)
                LDSM4(alf[mt][0], alf[mt][1], alf[mt][2], alf[mt][3], a_ad + 32);
        }
#pragma unroll
        for (int npp = 0; npp < 2; npp++) {
            uint32_t bhf[2][4], blf[2][4];
#pragma unroll
            for (int q = 0; q < 2; q++) {
                int row = wn * 64 + (npp * 2 + q) * 16 + l15;
                uint32_t b_ad = bsb + row * (SMSTR * 2) + l16 * 16;
                LDSM4(bhf[q][0], bhf[q][1], bhf[q][2], bhf[q][3], b_ad);
                if (full)
                    LDSM4(blf[q][0], blf[q][1], blf[q][2], blf[q][3], b_ad + 32);
            }
#pragma unroll
            for (int q = 0; q < 2; q++)
#pragma unroll
                for (int mt = 0; mt < 2; mt++)
#pragma unroll
                    for (int j = 0; j < 2; j++)
                        MMA16816(acc[mt][(npp * 2 + q) * 2 + j],
                                 ahf[mt][0], ahf[mt][1], ahf[mt][2], ahf[mt][3],
                                 bhf[q][j], bhf[q][2 + j]);
            if (full) {
#pragma unroll
                for (int q = 0; q < 2; q++)
#pragma unroll
                    for (int mt = 0; mt < 2; mt++)
#pragma unroll
                        for (int j = 0; j < 2; j++)
                            MMA16816(acc[mt][(npp * 2 + q) * 2 + j],
                                     ahf[mt][0], ahf[mt][1], ahf[mt][2], ahf[mt][3],
                                     blf[q][j], blf[q][2 + j]);
#pragma unroll
                for (int q = 0; q < 2; q++)
#pragma unroll
                    for (int mt = 0; mt < 2; mt++)
#pragma unroll
                        for (int j = 0; j < 2; j++)
                            MMA16816(acc[mt][(npp * 2 + q) * 2 + j],
                                     alf[mt][0], alf[mt][1], alf[mt][2], alf[mt][3],
                                     bhf[q][j], bhf[q][2 + j]);
            }
        }

        if (more) {
            if (!AHL) {
                const int nxt = 1 - cur;
                uint32_t h[4], l[4];
                split2(ra0.x, ra0.y, h[0], l[0]); split2(ra0.z, ra0.w, h[1], l[1]);
                split2(ra1.x, ra1.y, h[2], l[2]); split2(ra1.z, ra1.w, h[3], l[3]);
                uint4* ah = (uint4*)&As[nxt][srow * SMSTR + shalf * 8];
                ah[0] = make_uint4(h[0], h[1], h[2], h[3]);
                ah[2] = make_uint4(l[0], l[1], l[2], l[3]);
            }
            CPASYNC_WAIT0();
            __syncthreads();
        }
    }

    float ga = 0.f;
    if (p.act == 3) ga = 1.f / (1.f + __expf(-p.skipp[0]));
    const int hlstride = 256;

#pragma unroll
    for (int mt = 0; mt < 2; mt++) {
#pragma unroll
        for (int nt = 0; nt < 8; nt++) {
            int r0 = m0 + wm * 32 + mt * 16 + gq;
            int cc = n0 + wn * 64 + nt * 8 + 2 * tg;
            if (cc < p.N) {
                float b0 = p.bias ? p.bias[cc] : 0.f;
                float b1 = p.bias ? p.bias[cc + 1] : 0.f;
                float v0 = acc[mt][nt][0] + b0, v1 = acc[mt][nt][1] + b1;
                float v2 = acc[mt][nt][2] + b0, v3 = acc[mt][nt][3] + b1;
                if (p.act == 1) {
                    v0 = fmaxf(v0, 0.f); v1 = fmaxf(v1, 0.f);
                    v2 = fmaxf(v2, 0.f); v3 = fmaxf(v3, 0.f);
                } else if (p.act == 2) {
                    v0 = 1.f / (1.f + __expf(-v0)); v1 = 1.f / (1.f + __expf(-v1));
                    v2 = 1.f / (1.f + __expf(-v2)); v3 = 1.f / (1.f + __expf(-v3));
                } else if (p.act == 3) {
                    if (r0 < p.M) {
                        v0 = ga * v0 + (1.f - ga) * p.aux[(size_t)r0 * 256 + cc];
                        v1 = ga * v1 + (1.f - ga) * p.aux[(size_t)r0 * 256 + cc + 1];
                    }
                    if (r0 + 8 < p.M) {
                        v2 = ga * v2 + (1.f - ga) * p.aux[(size_t)(r0 + 8) * 256 + cc];
                        v3 = ga * v3 + (1.f - ga) * p.aux[(size_t)(r0 + 8) * 256 + cc + 1];
                    }
                }
                if (p.Ch) {
                    __half2* Ch = (__half2*)p.Ch;
                    if (r0 < p.M)
                        Ch[((size_t)r0 * p.ldc + cc) >> 1] = __floats2half2_rn(v0, v1);
                    if (r0 + 8 < p.M)
                        Ch[((size_t)(r0 + 8) * p.ldc + cc) >> 1] = __floats2half2_rn(v2, v3);
                }
                if (p.C) {
                    if (r0 < p.M) {
                        float2 q = {v0, v1};
                        *(float2*)&p.C[(size_t)r0 * p.ldc + cc] = q;
                    }
                    if (r0 + 8 < p.M) {
                        float2 q = {v2, v3};
                        *(float2*)&p.C[(size_t)(r0 + 8) * p.ldc + cc] = q;
                    }
                }
                if (p.Chl) {
                    int coff = (cc >> 4) * 16 + ((cc & 15) >> 1);
                    if (r0 < p.M) {
                        uint32_t hi, lo;
                        split2(v0, v1, hi, lo);
                        uint32_t* d = (uint32_t*)p.Chl + (size_t)r0 * hlstride + coff;
                        d[0] = hi; d[8] = lo;
                    }
                    if (r0 + 8 < p.M) {
                        uint32_t hi, lo;
                        split2(v2, v3, hi, lo);
                        uint32_t* d = (uint32_t*)p.Chl + (size_t)(r0 + 8) * hlstride + coff;
                        d[0] = hi; d[8] = lo;
                    }
                }
            }
        }
    }
}

__global__ void tr_all(const float* __restrict__ Wp, const float* __restrict__ Wa,
                       const float* __restrict__ Wq, const float* __restrict__ Wo)
{
    __shared__ float t[32][33];
    const float* in; __nv_bfloat16* out; int ldin, K, N;
    switch (blockIdx.z) {
        case 0: in = Wp; out = g_winp_hl; ldin = 256; K = 128; N = 256; break;
        case 1: in = Wa; out = g_wina_hl; ldin = 256; K = 128; N = 256; break;
        case 2: in = Wq; out = g_wq_hl;   ldin = 768; K = 256; N = 256; break;
        default: in = Wo; out = g_wout_hl; ldin = 256; K = 256; N = 256; break;
    }
    int bx = blockIdx.x * 32, by = blockIdx.y * 32;
    if (bx >= N || by >= K) return;
    int x = bx + threadIdx.x;
    for (int dy = 0; dy < 32; dy += 8) {
        int y = by + threadIdx.y + dy;
        if (x < N && y < K) t[threadIdx.y + dy][threadIdx.x] = in[(size_t)y * ldin + x];
    }
    __syncthreads();
    if (threadIdx.x < 16) {
        for (int dy = 0; dy < 32; dy += 8) {
            int n_ = bx + threadIdx.y + dy;
            int k0 = by + 2 * threadIdx.x;
            if (n_ < N && k0 < K) {
                float f0 = t[2 * threadIdx.x][threadIdx.y + dy];
                float f1 = t[2 * threadIdx.x + 1][threadIdx.y + dy];
                uint32_t hi, lo;
                split2(f0, f1, hi, lo);
                uint32_t* d = (uint32_t*)(out + (size_t)n_ * 2 * K
                                          + (k0 >> 4) * 32 + (k0 & 15));
                d[0] = hi; d[8] = lo;
            }
        }
    }
}

__global__ void fuse_kernel(const float* __restrict__ Wkqv_p,
                            const float* __restrict__ Rk,
                            const float* __restrict__ Rv)
{
    int idx = blockIdx.x * 256 + threadIdx.x;
    int c = idx >> 7;
    int j = idx & 127;
    int isv = c >> 8, h = (c >> 7) & 1, e = c & 127;
    const float* R = (isv ? Rv : Rk) + h * 16384;
    const float* w0 = Wkqv_p + (size_t)(2 * j) * 768 + (isv ? 512 : 0) + h * 128;
    const float* w1 = w0 + 768;
    float s0 = 0.f, s1 = 0.f;
#pragma unroll 8
    for (int d = 0; d < 128; d++) {
        float rv = R[d * 128 + e];
        s0 += w0[d] * rv;
        s1 += w1[d] * rv;
    }
    uint32_t hi, lo;
    split2(s0, s1, hi, lo);
    int k = 2 * j;
    uint32_t* dst = (uint32_t*)(g_wft_hl + (size_t)c * 512 + (k >> 4) * 32 + (k & 15));
    dst[0] = hi; dst[8] = lo;
}

__global__ void bias_fuse_kernel(const float* __restrict__ bkqv,
                                 const float* __restrict__ Rk,
                                 const float* __restrict__ Rv)
{
    int gw = (blockIdx.x * 256 + threadIdx.x) >> 5;
    int lane = threadIdx.x & 31;
    if (gw >= 512) return;
    int isv = gw >> 8, h = (gw >> 7) & 1, e = gw & 127;
    const float* R = (isv ? Rv : Rk) + h * 16384;
    const float* b = bkqv + (isv ? 512 : 0) + h * 128;
    float s = 0.f;
#pragma unroll
    for (int i = 0; i < 4; i++) {
        int d = lane + 32 * i;
        s += b[d] * R[d * 128 + e];
    }
#pragma unroll
    for (int o = 16; o > 0; o >>= 1) s += __shfl_xor_sync(0xffffffffu, s, o);
    if (lane == 0) g_bf[gw] = s;
}

__global__ void zero_deg_kernel(int n)
{
    int i = blockIdx.x * blockDim.x + threadIdx.x;
    if (i <= n) g_deg[i] = 0;
}
__global__ void hist_kernel(const int* __restrict__ dst, int E)
{
    int e = blockIdx.x * blockDim.x + threadIdx.x;
    if (e < E) atomicAdd(&g_deg[dst[e]], 1);
}
__global__ void __launch_bounds__(1024) scan_kernel(int n)
{
    __shared__ int part[1024];
    int t = threadIdx.x;
    int chunk = (n + 1023) >> 10;
    int b = t * chunk, e = min(b + chunk, n);
    int s = 0;
    for (int i = b; i < e; i++) s += g_deg[i];
    part[t] = s;
    __syncthreads();
    for (int o = 1; o < 1024; o <<= 1) {
        int v = (t >= o) ? part[t - o] : 0;
        __syncthreads();
        part[t] += v;
        __syncthreads();
    }
    int run = (t == 0) ? 0 : part[t - 1];
    for (int i = b; i < e; i++) {
        g_off[i] = run; g_cur[i] = run; run += g_deg[i];
    }
    if (t == 0) g_off[n] = part[1023];
}
__global__ void scatter_kernel(const int* __restrict__ src,
                               const int* __restrict__ dst, int E)
{
    int e = blockIdx.x * blockDim.x + threadIdx.x;
    if (e < E) {
        int p = atomicAdd(&g_cur[dst[e]], 1);
        g_csr[p] = src[e];
    }
}

__device__ __forceinline__ float dot8h(const float4& q0, const float4& q1,
                                       const uint4& ck)
{
    float2 k0 = __half22float2(*(const __half2*)&ck.x);
    float2 k1 = __half22float2(*(const __half2*)&ck.y);
    float2 k2 = __half22float2(*(const __half2*)&ck.z);
    float2 k3 = __half22float2(*(const __half2*)&ck.w);
    return q0.x * k0.x + q0.y * k0.y + q0.z * k1.x + q0.w * k1.y
         + q1.x * k2.x + q1.y * k2.y + q1.z * k3.x + q1.w * k3.y;
}

__device__ __forceinline__ void acc8h(float (&a)[8], float w, const uint4& cv)
{
    float2 v0 = __half22float2(*(const __half2*)&cv.x);
    float2 v1 = __half22float2(*(const __half2*)&cv.y);
    float2 v2 = __half22float2(*(const __half2*)&cv.z);
    float2 v3 = __half22float2(*(const __half2*)&cv.w);
    a[0] += w * v0.x; a[1] += w * v0.y;
    a[2] += w * v1.x; a[3] += w * v1.y;
    a[4] += w * v2.x; a[5] += w * v2.y;
    a[6] += w * v3.x; a[7] += w * v3.y;
}

__global__ void attn_kernel(int Na, const float* __restrict__ p_rel)
{
    int gw = (blockIdx.x * 256 + threadIdx.x) >> 5;
    int lane = threadIdx.x & 31;
    if (gw >= Na) return;
    const int dst = gw;
    const int hl = lane >> 4;
    const int l  = lane & 15;

    const int beg = g_off[dst], end = g_off[dst + 1];
    const float scale = p_rel[hl] * 0.08838834764831845f;

    // q in fp16 (one 16B load)
    const __half* qb = &g_qah[(size_t)dst * 256 + hl * 128 + l * 8];
    uint4 qraw = *(const uint4*)qb;
    float2 qx = __half22float2(*(const __half2*)&qraw.x);
    float2 qy = __half22float2(*(const __half2*)&qraw.y);
    float2 qz = __half22float2(*(const __half2*)&qraw.z);
    float2 qw = __half22float2(*(const __half2*)&qraw.w);
    const float4 q0 = make_float4(qx.x, qx.y, qy.x, qy.y);
    const float4 q1 = make_float4(qz.x, qz.y, qw.x, qw.y);

    float m = -INFINITY, ssum = 0.f;
    float a[8] = {0.f, 0.f, 0.f, 0.f, 0.f, 0.f, 0.f, 0.f};

    const size_t base_off = (size_t)hl * 128 + l * 8;

    int p = beg;
    for (; p + 4 <= end; p += 4) {
        const __half* kb0 = &g_kvh[(size_t)g_csr[p]     * 512 + base_off];
        const __half* kb1 = &g_kvh[(size_t)g_csr[p + 1] * 512 + base_off];
        const __half* kb2 = &g_kvh[(size_t)g_csr[p + 2] * 512 + base_off];
        const __half* kb3 = &g_kvh[(size_t)g_csr[p + 3] * 512 + base_off];
        uint4 ck0 = *(const uint4*)kb0, cv0 = *(const uint4*)(kb0 + 256);
        uint4 ck1 = *(const uint4*)kb1, cv1 = *(const uint4*)(kb1 + 256);
        uint4 ck2 = *(const uint4*)kb2, cv2 = *(const uint4*)(kb2 + 256);
        uint4 ck3 = *(const uint4*)kb3, cv3 = *(const uint4*)(kb3 + 256);

        float d0 = dot8h(q0, q1, ck0);
        float d1 = dot8h(q0, q1, ck1);
        float d2 = dot8h(q0, q1, ck2);
        float d3 = dot8h(q0, q1, ck3);
#pragma unroll
        for (int o = 8; o > 0; o >>= 1) {
            d0 += __shfl_xor_sync(0xffffffffu, d0, o);
            d1 += __shfl_xor_sync(0xffffffffu, d1, o);
            d2 += __shfl_xor_sync(0xffffffffu, d2, o);
            d3 += __shfl_xor_sync(0xffffffffu, d3, o);
        }
        d0 *= scale; d1 *= scale; d2 *= scale; d3 *= scale;
        float mx = fmaxf(fmaxf(d0, d1), fmaxf(d2, d3));
        float mn = fmaxf(m, mx);
        float corr = __expf(m - mn);
        float w0 = __expf(d0 - mn), w1 = __expf(d1 - mn);
        float w2 = __expf(d2 - mn), w3 = __expf(d3 - mn);
        ssum = ssum * corr + w0 + w1 + w2 + w3;
#pragma unroll
        for (int j = 0; j < 8; j++) a[j] *= corr;
        acc8h(a, w0, cv0); acc8h(a, w1, cv1);
        acc8h(a, w2, cv2); acc8h(a, w3, cv3);
        m = mn;
    }
    for (; p < end; p++) {
        const __half* kb = &g_kvh[(size_t)g_csr[p] * 512 + base_off];
        uint4 ck = *(const uint4*)kb, cv = *(const uint4*)(kb + 256);
        float d = dot8h(q0, q1, ck);
#pragma unroll
        for (int o = 8; o > 0; o >>= 1) d += __shfl_xor_sync(0xffffffffu, d, o);
        d *= scale;
        float mn = fmaxf(m, d);
        float corr = __expf(m - mn);
        float w = __expf(d - mn);
        ssum = ssum * corr + w;
#pragma unroll
        for (int j = 0; j < 8; j++) a[j] *= corr;
        acc8h(a, w, cv);
        m = mn;
    }

    float inv = 1.f / (ssum + 1e-16f);
#pragma unroll
    for (int j = 0; j < 8; j++) {
        float o = a[j] * inv;
        a[j] = 0.5f * o * (1.f + erff(o * 0.7071067811865475f));
    }
    const int k = hl * 128 + l * 8;
    uint32_t hi[4], lo[4];
    split2(a[0], a[1], hi[0], lo[0]);
    split2(a[2], a[3], hi[1], lo[1]);
    split2(a[4], a[5], hi[2], lo[2]);
    split2(a[6], a[7], hi[3], lo[3]);
    uint32_t* d = (uint32_t*)g_agg_hl + (size_t)dst * 256
                + (k >> 4) * 16 + ((k & 15) >> 1);
    *(uint4*)d       = make_uint4(hi[0], hi[1], hi[2], hi[3]);
    *(uint4*)(d + 8) = make_uint4(lo[0], lo[1], lo[2], lo[3]);
}

// Decoder rows: za read from hl format (hi + lo reconstruct)
__global__ void zin_kernel(const int* __restrict__ nodes,
                           const float* __restrict__ Wdec,
                           const float* __restrict__ bdec)
{
    __shared__ float row[256];
    int r = blockIdx.x, t = threadIdx.x;
    {
        const uint32_t* zr = (const uint32_t*)g_za_hl + (size_t)nodes[r] * 256;
        int w = (t >> 4) * 16 + ((t & 15) >> 1);
        uint32_t hw = zr[w], lw = zr[w + 8];
        __nv_bfloat16 hb = ((const __nv_bfloat16*)&hw)[t & 1];
        __nv_bfloat16 lb = ((const __nv_bfloat16*)&lw)[t & 1];
        row[t] = __bfloat162float(hb) + __bfloat162float(lb);
    }
    __syncthreads();
    float s = bdec[t];
#pragma unroll 8
    for (int k = 0; k < 256; k++) s += row[k] * Wdec[k * 256 + t];
    float s1 = __shfl_xor_sync(0xffffffffu, s, 1);
    if ((t & 1) == 0) {
        uint32_t hi, lo;
        split2(s, s1, hi, lo);
        uint32_t* d = (uint32_t*)g_zin_hl + (size_t)r * 256
                    + (t >> 4) * 16 + ((t & 15) >> 1);
        d[0] = hi; d[8] = lo;
    }
}

static inline GP mkgp(const float* A, int lda, const __nv_bfloat16* Ahl,
                      const __nv_bfloat16* B,
                      float* C, __half* Ch, __nv_bfloat16* Chl, int ldc,
                      const float* bias, int act, int M, int N, int K, int terms,
                      const float* aux = nullptr, const float* skipp = nullptr)
{
    GP p; p.A = A; p.lda = lda; p.Ahl = Ahl; p.B = B;
    p.C = C; p.Ch = Ch; p.Chl = Chl; p.ldc = ldc;
    p.bias = bias; p.act = act; p.M = M; p.N = N; p.K = K; p.terms = terms;
    p.aux = aux; p.skipp = skipp;
    return p;
}

extern "C" void kernel_launch(void* const* d_in, const int* in_sizes, int n_in,
                              void* d_out, int out_size)
{
    const float* x_author    = (const float*)d_in[0];
    const float* x_paper     = (const float*)d_in[1];
    const int*   edge_b_src  = (const int*)d_in[4];
    const int*   edge_b_dst  = (const int*)d_in[5];
    const int*   input_nodes = (const int*)d_in[6];
    const float* W_in_a  = (const float*)d_in[7];
    const float* b_in_a  = (const float*)d_in[8];
    const float* W_in_p  = (const float*)d_in[9];
    const float* b_in_p  = (const float*)d_in[10];
    const float* Wkqv_a  = (const float*)d_in[11];
    const float* bkqv_a  = (const float*)d_in[12];
    const float* Wkqv_p  = (const float*)d_in[13];
    const float* bkqv_p  = (const float*)d_in[14];
    const float* Wk_rel_b = (const float*)d_in[17];
    const float* Wv_rel_b = (const float*)d_in[18];
    const float* p_b     = (const float*)d_in[20];
    const float* Wout_a  = (const float*)d_in[21];
    const float* bout_a  = (const float*)d_in[22];
    const float* skip_a  = (const float*)d_in[25];
    const float* W_dec   = (const float*)d_in[27];
    const float* b_dec   = (const float*)d_in[28];

    const int Na = in_sizes[0] / 128;
    const int Np = in_sizes[1] / 128;
    const int E  = in_sizes[4];
    const int NI = in_sizes[6];

    float *xp, *xa, *bf;
    __half *kvh, *qah;
    __nv_bfloat16 *agg_hl, *za_hl, *zin_hl;
    __nv_bfloat16 *wft_hl, *winp_hl, *wina_hl, *wq_hl, *wout_hl;
    cudaGetSymbolAddress((void**)&xp,  g_xp);
    cudaGetSymbolAddress((void**)&xa,  g_xa);
    cudaGetSymbolAddress((void**)&qah, g_qah);
    cudaGetSymbolAddress((void**)&kvh, g_kvh);
    cudaGetSymbolAddress((void**)&bf,  g_bf);
    cudaGetSymbolAddress((void**)&agg_hl, g_agg_hl);
    cudaGetSymbolAddress((void**)&za_hl,  g_za_hl);
    cudaGetSymbolAddress((void**)&zin_hl, g_zin_hl);
    cudaGetSymbolAddress((void**)&wft_hl,  g_wft_hl);
    cudaGetSymbolAddress((void**)&winp_hl, g_winp_hl);
    cudaGetSymbolAddress((void**)&wina_hl, g_wina_hl);
    cudaGetSymbolAddress((void**)&wq_hl,   g_wq_hl);
    cudaGetSymbolAddress((void**)&wout_hl, g_wout_hl);

    // Fork CSR build onto a side stream (event-based, graph-capturable).
    // Fresh stream/events per call: kernel_launch runs only for correctness
    // + capture, never inside the timed replay, so no allocation-guard issue
    // (host objects only) and no statics.
    cudaStream_t s2;
    cudaEvent_t e0, e1;
    cudaStreamCreateWithFlags(&s2, cudaStreamNonBlocking);
    cudaEventCreateWithFlags(&e0, cudaEventDisableTiming);
    cudaEventCreateWithFlags(&e1, cudaEventDisableTiming);

    cudaEventRecord(e0, 0);
    cudaStreamWaitEvent(s2, e0, 0);
    zero_deg_kernel<<<(Na + 256) / 256, 256, 0, s2>>>(Na);
    hist_kernel<<<(E + 255) / 256, 256, 0, s2>>>(edge_b_dst, E);
    scan_kernel<<<1, 1024, 0, s2>>>(Na);
    scatter_kernel<<<(E + 255) / 256, 256, 0, s2>>>(edge_b_src, edge_b_dst, E);
    cudaEventRecord(e1, s2);

    // Main stream: weight prep + projections
    fuse_kernel<<<256, 256>>>(Wkqv_p, Wk_rel_b, Wv_rel_b);
    tr_all<<<dim3(8, 8, 4), dim3(32, 8)>>>(W_in_p, W_in_a, Wkqv_a + 256, Wout_a);
    bias_fuse_kernel<<<64, 256>>>(bkqv_p, Wk_rel_b, Wv_rel_b);

    {
        GP pxp = mkgp(x_paper,  128, nullptr, winp_hl,
                      xp, nullptr, nullptr, 256, b_in_p, 1, Np, 256, 128, 3);
        GP pxa = mkgp(x_author, 128, nullptr, wina_hl,
                      xa, nullptr, nullptr, 256, b_in_a, 1, Na, 256, 128, 3);
        int gy = (Na > Np ? Na : Np);
        mm_nt<false><<<dim3(2, (gy + 127) / 128, 2), 256>>>(pxp, pxa);
    }
    {
        GP pkv = mkgp(xp, 256, nullptr, wft_hl,
                      nullptr, kvh, nullptr, 512, bf, 0, Np, 512, 256, 3);
        GP pqa = mkgp(xa, 256, nullptr, wq_hl,
                      nullptr, qah, nullptr, 256, bkqv_a + 256, 0, Na, 256, 256, 3);
        int gy = (Na > Np ? Na : Np);
        mm_nt<false><<<dim3(4, (gy + 127) / 128, 2), 256>>>(pkv, pqa);
    }

    // Join: attention needs CSR + kv + qa
    cudaStreamWaitEvent(0, e1, 0);
    {
        int blocks = (Na * 32 + 255) / 256;
        attn_kernel<<<blocks, 256>>>(Na, p_b);
    }
    // za gated residual: A = agg_hl, hl out only (no fp32 store)
    {
        GP pw = mkgp(nullptr, 0, agg_hl, wout_hl,
                     nullptr, nullptr, za_hl, 256, bout_a, 3, Na, 256, 256, 3,
                     xa, skip_a);
        mm_nt<true><<<dim3(2, (Na + 127) / 128, 1), 256>>>(pw, pw);
    }
    zin_kernel<<<NI, 256>>>(input_nodes, W_dec, b_dec);
    {
        GP pf = mkgp(nullptr, 0, zin_hl, za_hl,
                     (float*)d_out, nullptr, nullptr, Na, nullptr, 2,
                     NI, Na, 256, 3);
        mm_nt<true><<<dim3((Na + 127) / 128, (NI + 127) / 128, 1), 256>>>(pf, pf);
    }
}